// round 1
// baseline (speedup 1.0000x reference)
#include <cuda_runtime.h>

#define D_MODEL   1024
#define NUM_HEADS 16
#define D_HEAD    64
#define BATCH     2
#define SEQ       2048
#define ROWS      (BATCH * SEQ)   // 4096

// Scratch (alloc-free rule: __device__ globals)
__device__ float g_qkv[(size_t)ROWS * 3 * D_MODEL];   // 48 MB
__device__ float g_y[(size_t)ROWS * D_MODEL];         // 16 MB

// ---------------------------------------------------------------------------
// SGEMM NT: C[m,n] = sum_k A[m,k] * B[n,k]   (A:[M,K], B:[N,K], both K-major)
// 128x128 block, BK=16, 256 threads, 8x8 microtile, smem stored K-major
// so inner-loop fragment loads are coalesced LDS.128.
// ---------------------------------------------------------------------------
__global__ __launch_bounds__(256) void gemm_nt128(const float* __restrict__ A,
                                                  const float* __restrict__ B,
                                                  float* __restrict__ C,
                                                  int M, int N, int K) {
    constexpr int BM = 128, BN = 128, BK = 16;
    __shared__ float Ast[BK][BM + 4];
    __shared__ float Bst[BK][BN + 4];

    const int tid = threadIdx.x;
    const int tx = tid & 15;
    const int ty = tid >> 4;
    const int m0 = blockIdx.y * BM;
    const int n0 = blockIdx.x * BN;

    float acc[8][8];
#pragma unroll
    for (int i = 0; i < 8; i++)
#pragma unroll
        for (int j = 0; j < 8; j++) acc[i][j] = 0.f;

    for (int k0 = 0; k0 < K; k0 += BK) {
#pragma unroll
        for (int li = 0; li < 2; li++) {
            int vec = li * 256 + tid;          // 0..511
            int row = vec >> 2;                // 0..127
            int kv  = (vec & 3) * 4;           // 0,4,8,12
            float4 av = *(const float4*)&A[(size_t)(m0 + row) * K + k0 + kv];
            Ast[kv + 0][row] = av.x; Ast[kv + 1][row] = av.y;
            Ast[kv + 2][row] = av.z; Ast[kv + 3][row] = av.w;
            float4 bv = *(const float4*)&B[(size_t)(n0 + row) * K + k0 + kv];
            Bst[kv + 0][row] = bv.x; Bst[kv + 1][row] = bv.y;
            Bst[kv + 2][row] = bv.z; Bst[kv + 3][row] = bv.w;
        }
        __syncthreads();

#pragma unroll
        for (int kk = 0; kk < BK; kk++) {
            float a[8], b[8];
            *(float4*)&a[0] = *(const float4*)&Ast[kk][ty * 8];
            *(float4*)&a[4] = *(const float4*)&Ast[kk][ty * 8 + 4];
            *(float4*)&b[0] = *(const float4*)&Bst[kk][tx * 8];
            *(float4*)&b[4] = *(const float4*)&Bst[kk][tx * 8 + 4];
#pragma unroll
            for (int i = 0; i < 8; i++)
#pragma unroll
                for (int j = 0; j < 8; j++)
                    acc[i][j] = fmaf(a[i], b[j], acc[i][j]);
        }
        __syncthreads();
    }

#pragma unroll
    for (int i = 0; i < 8; i++) {
        int m = m0 + ty * 8 + i;
#pragma unroll
        for (int j = 0; j < 8; j += 4) {
            float4 v = make_float4(acc[i][j], acc[i][j + 1], acc[i][j + 2], acc[i][j + 3]);
            *(float4*)&C[(size_t)m * N + n0 + tx * 8 + j] = v;
        }
    }
}

// ---------------------------------------------------------------------------
// Flash attention (causal), fp32. BQ=BK=64, Dh=64, 256 threads, 4x4 microtile.
// Q/K/V read directly out of the packed qkv buffer (q @ +0, k @ +1024, v @ +2048).
// K stored transposed in smem so S-compute inner loads are LDS.128.
// ---------------------------------------------------------------------------
__global__ __launch_bounds__(256) void attn_kernel(const float* __restrict__ qkv,
                                                   float* __restrict__ y) {
    constexpr int BQ = 64, BKT = 64, DH = 64, LD = DH + 4;   // 68
    extern __shared__ float sm[];
    float* Qs = sm;                 // [BQ][LD]
    float* Kt = Qs + BQ * LD;       // [DH][LD]  (Kt[d][j])
    float* Vs = Kt + DH * LD;       // [BKT][LD]
    float* Ps = Vs + BKT * LD;      // [BQ][LD]

    const int tid = threadIdx.x;
    const int tx = tid & 15;
    const int ty = tid >> 4;
    const int qt = blockIdx.x;
    const int h  = blockIdx.y;
    const int b  = blockIdx.z;
    const int q0 = qt * BQ;
    const float scale = 0.125f;   // 1/sqrt(64)

    const size_t rowstride = 3 * D_MODEL;
    const float* qbase = qkv + (size_t)b * SEQ * rowstride + h * D_HEAD;
    const float* kbase = qbase + D_MODEL;
    const float* vbase = qbase + 2 * D_MODEL;

    // Load Q tile (pre-scaled)
#pragma unroll
    for (int li = 0; li < 4; li++) {
        int vec = li * 256 + tid;       // 0..1023
        int i = vec >> 4;               // 0..63
        int d = (vec & 15) * 4;         // 0..60
        float4 v = *(const float4*)&qbase[(size_t)(q0 + i) * rowstride + d];
        v.x *= scale; v.y *= scale; v.z *= scale; v.w *= scale;
        *(float4*)&Qs[i * LD + d] = v;
    }

    float acc[4][4];
    float mrow[4], lrow[4];
#pragma unroll
    for (int r = 0; r < 4; r++) {
        mrow[r] = -1e9f; lrow[r] = 0.f;
#pragma unroll
        for (int c = 0; c < 4; c++) acc[r][c] = 0.f;
    }

    const int ntiles = qt + 1;
    for (int kt = 0; kt < ntiles; kt++) {
        const int k0 = kt * BKT;
        __syncthreads();   // prior-iteration Ps/Vs reads done (also covers Q at kt=0)

        // Load K (transposed) and V tiles
#pragma unroll
        for (int li = 0; li < 4; li++) {
            int vec = li * 256 + tid;
            int j = vec >> 4;
            int d = (vec & 15) * 4;
            float4 kv = *(const float4*)&kbase[(size_t)(k0 + j) * rowstride + d];
            Kt[(d + 0) * LD + j] = kv.x;
            Kt[(d + 1) * LD + j] = kv.y;
            Kt[(d + 2) * LD + j] = kv.z;
            Kt[(d + 3) * LD + j] = kv.w;
            float4 vv = *(const float4*)&vbase[(size_t)(k0 + j) * rowstride + d];
            *(float4*)&Vs[j * LD + d] = vv;
        }
        __syncthreads();

        // S = Q K^T  (4x4 per thread)
        float s[4][4];
#pragma unroll
        for (int r = 0; r < 4; r++)
#pragma unroll
            for (int c = 0; c < 4; c++) s[r][c] = 0.f;

#pragma unroll 8
        for (int d = 0; d < DH; d++) {
            float a0 = Qs[(ty * 4 + 0) * LD + d];
            float a1 = Qs[(ty * 4 + 1) * LD + d];
            float a2 = Qs[(ty * 4 + 2) * LD + d];
            float a3 = Qs[(ty * 4 + 3) * LD + d];
            float4 k4 = *(const float4*)&Kt[d * LD + tx * 4];
            s[0][0] = fmaf(a0, k4.x, s[0][0]); s[0][1] = fmaf(a0, k4.y, s[0][1]);
            s[0][2] = fmaf(a0, k4.z, s[0][2]); s[0][3] = fmaf(a0, k4.w, s[0][3]);
            s[1][0] = fmaf(a1, k4.x, s[1][0]); s[1][1] = fmaf(a1, k4.y, s[1][1]);
            s[1][2] = fmaf(a1, k4.z, s[1][2]); s[1][3] = fmaf(a1, k4.w, s[1][3]);
            s[2][0] = fmaf(a2, k4.x, s[2][0]); s[2][1] = fmaf(a2, k4.y, s[2][1]);
            s[2][2] = fmaf(a2, k4.z, s[2][2]); s[2][3] = fmaf(a2, k4.w, s[2][3]);
            s[3][0] = fmaf(a3, k4.x, s[3][0]); s[3][1] = fmaf(a3, k4.y, s[3][1]);
            s[3][2] = fmaf(a3, k4.z, s[3][2]); s[3][3] = fmaf(a3, k4.w, s[3][3]);
        }

        // Causal mask (only on diagonal tile)
        if (kt == qt) {
#pragma unroll
            for (int r = 0; r < 4; r++) {
                int qr = q0 + ty * 4 + r;
#pragma unroll
                for (int c = 0; c < 4; c++) {
                    int kc = k0 + tx * 4 + c;
                    if (kc > qr) s[r][c] = -1e9f;
                }
            }
        }

        // Online softmax (row stats reduced across the 16 tx lanes)
#pragma unroll
        for (int r = 0; r < 4; r++) {
            float mx = fmaxf(fmaxf(s[r][0], s[r][1]), fmaxf(s[r][2], s[r][3]));
            mx = fmaxf(mx, __shfl_xor_sync(0xffffffffu, mx, 1));
            mx = fmaxf(mx, __shfl_xor_sync(0xffffffffu, mx, 2));
            mx = fmaxf(mx, __shfl_xor_sync(0xffffffffu, mx, 4));
            mx = fmaxf(mx, __shfl_xor_sync(0xffffffffu, mx, 8));
            float mnew = fmaxf(mrow[r], mx);
            float corr = __expf(mrow[r] - mnew);
            mrow[r] = mnew;
            float ls = 0.f;
#pragma unroll
            for (int c = 0; c < 4; c++) {
                float p = __expf(s[r][c] - mnew);
                s[r][c] = p;
                ls += p;
            }
            ls += __shfl_xor_sync(0xffffffffu, ls, 1);
            ls += __shfl_xor_sync(0xffffffffu, ls, 2);
            ls += __shfl_xor_sync(0xffffffffu, ls, 4);
            ls += __shfl_xor_sync(0xffffffffu, ls, 8);
            lrow[r] = lrow[r] * corr + ls;
#pragma unroll
            for (int c = 0; c < 4; c++) acc[r][c] *= corr;
            *(float4*)&Ps[(ty * 4 + r) * LD + tx * 4] =
                make_float4(s[r][0], s[r][1], s[r][2], s[r][3]);
        }
        __syncthreads();

        // O += P V
#pragma unroll 8
        for (int j = 0; j < BKT; j++) {
            float p0 = Ps[(ty * 4 + 0) * LD + j];
            float p1 = Ps[(ty * 4 + 1) * LD + j];
            float p2 = Ps[(ty * 4 + 2) * LD + j];
            float p3 = Ps[(ty * 4 + 3) * LD + j];
            float4 v4 = *(const float4*)&Vs[j * LD + tx * 4];
            acc[0][0] = fmaf(p0, v4.x, acc[0][0]); acc[0][1] = fmaf(p0, v4.y, acc[0][1]);
            acc[0][2] = fmaf(p0, v4.z, acc[0][2]); acc[0][3] = fmaf(p0, v4.w, acc[0][3]);
            acc[1][0] = fmaf(p1, v4.x, acc[1][0]); acc[1][1] = fmaf(p1, v4.y, acc[1][1]);
            acc[1][2] = fmaf(p1, v4.z, acc[1][2]); acc[1][3] = fmaf(p1, v4.w, acc[1][3]);
            acc[2][0] = fmaf(p2, v4.x, acc[2][0]); acc[2][1] = fmaf(p2, v4.y, acc[2][1]);
            acc[2][2] = fmaf(p2, v4.z, acc[2][2]); acc[2][3] = fmaf(p2, v4.w, acc[2][3]);
            acc[3][0] = fmaf(p3, v4.x, acc[3][0]); acc[3][1] = fmaf(p3, v4.y, acc[3][1]);
            acc[3][2] = fmaf(p3, v4.z, acc[3][2]); acc[3][3] = fmaf(p3, v4.w, acc[3][3]);
        }
    }

    // Normalize + write y in [B,T,D_MODEL] layout (heads re-interleaved)
#pragma unroll
    for (int r = 0; r < 4; r++) {
        float inv = 1.f / lrow[r];
        float4 o = make_float4(acc[r][0] * inv, acc[r][1] * inv,
                               acc[r][2] * inv, acc[r][3] * inv);
        size_t t = (size_t)b * SEQ + q0 + ty * 4 + r;
        *(float4*)&y[t * D_MODEL + h * D_HEAD + tx * 4] = o;
    }
}

// ---------------------------------------------------------------------------
extern "C" void kernel_launch(void* const* d_in, const int* in_sizes, int n_in,
                              void* d_out, int out_size) {
    const float* x    = (const float*)d_in[0];
    const float* Wqkv = (const float*)d_in[1];
    const float* Wout = (const float*)d_in[2];
    float* out = (float*)d_out;

    float *qkv, *y;
    cudaGetSymbolAddress((void**)&qkv, g_qkv);
    cudaGetSymbolAddress((void**)&y, g_y);

    // 1) QKV projection: [4096,1024] x [3072,1024]^T -> [4096,3072]
    gemm_nt128<<<dim3(3 * D_MODEL / 128, ROWS / 128), 256>>>(
        x, Wqkv, qkv, ROWS, 3 * D_MODEL, D_MODEL);

    // 2) Causal flash attention -> y [4096,1024]
    int shmem = 4 * 64 * 68 * (int)sizeof(float);   // 69632 B
    cudaFuncSetAttribute(attn_kernel, cudaFuncAttributeMaxDynamicSharedMemorySize, shmem);
    attn_kernel<<<dim3(SEQ / 64, NUM_HEADS, BATCH), 256, shmem>>>(qkv, y);

    // 3) Output projection: [4096,1024] x [1024,1024]^T -> [4096,1024]
    gemm_nt128<<<dim3(D_MODEL / 128, ROWS / 128), 256>>>(
        y, Wout, out, ROWS, D_MODEL, D_MODEL);
}

// round 3
// speedup vs baseline: 1.4362x; 1.4362x over previous
#include <cuda_runtime.h>
#include <cuda_bf16.h>
#include <cstdint>

#define D_MODEL   1024
#define NUM_HEADS 16
#define D_HEAD    64
#define BATCH     2
#define SEQ       2048
#define ROWS      (BATCH * SEQ)   // 4096

// ---------------------------------------------------------------------------
// Scratch (alloc-free rule: __device__ globals)
// ---------------------------------------------------------------------------
__device__ float g_qkv[(size_t)ROWS * 3 * D_MODEL];   // fp32 QKV
__device__ float g_y[(size_t)ROWS * D_MODEL];         // fp32 attention out

__device__ __nv_bfloat16 g_xh[(size_t)ROWS * D_MODEL];
__device__ __nv_bfloat16 g_xl[(size_t)ROWS * D_MODEL];
__device__ __nv_bfloat16 g_w1h[(size_t)3 * D_MODEL * D_MODEL];
__device__ __nv_bfloat16 g_w1l[(size_t)3 * D_MODEL * D_MODEL];
__device__ __nv_bfloat16 g_w2h[(size_t)D_MODEL * D_MODEL];
__device__ __nv_bfloat16 g_w2l[(size_t)D_MODEL * D_MODEL];
__device__ __nv_bfloat16 g_yh[(size_t)ROWS * D_MODEL];
__device__ __nv_bfloat16 g_yl[(size_t)ROWS * D_MODEL];

// ---------------------------------------------------------------------------
__device__ __forceinline__ uint32_t smem_u32(const void* p) {
    uint32_t a;
    asm("{ .reg .u64 t; cvta.to.shared.u64 t, %1; cvt.u32.u64 %0, t; }"
        : "=r"(a) : "l"(p));
    return a;
}

__device__ __forceinline__ void cp_async16(uint32_t dst, const void* src) {
    asm volatile("cp.async.cg.shared.global [%0], [%1], 16;" :: "r"(dst), "l"(src));
}

__device__ __forceinline__ void mma16816(float* c, const uint32_t* a, const uint32_t* b) {
    asm volatile(
        "mma.sync.aligned.m16n8k16.row.col.f32.bf16.bf16.f32 "
        "{%0,%1,%2,%3}, {%4,%5,%6,%7}, {%8,%9}, {%0,%1,%2,%3};"
        : "+f"(c[0]), "+f"(c[1]), "+f"(c[2]), "+f"(c[3])
        : "r"(a[0]), "r"(a[1]), "r"(a[2]), "r"(a[3]), "r"(b[0]), "r"(b[1]));
}

// ---------------------------------------------------------------------------
// Split fp32 -> bf16 hi/lo
// ---------------------------------------------------------------------------
__global__ __launch_bounds__(256) void split_bf16(const float* __restrict__ src,
                                                  __nv_bfloat16* __restrict__ hi,
                                                  __nv_bfloat16* __restrict__ lo,
                                                  int n4) {
    int i = blockIdx.x * blockDim.x + threadIdx.x;
    if (i >= n4) return;
    float4 v = ((const float4*)src)[i];
    float f[4] = {v.x, v.y, v.z, v.w};
    __nv_bfloat16 h[4], l[4];
#pragma unroll
    for (int j = 0; j < 4; j++) {
        h[j] = __float2bfloat16(f[j]);
        l[j] = __float2bfloat16(f[j] - __bfloat162float(h[j]));
    }
    ((uint2*)hi)[i] = *(uint2*)h;
    ((uint2*)lo)[i] = *(uint2*)l;
}

// ---------------------------------------------------------------------------
// Tensor-core GEMM NT via mma.sync (bf16, 3-term hi/lo compensation):
//   C[m,n] = sum_k A[m,k]*B[n,k]
// Block tile 128x128, BK=32, 8 warps (warp tile 64x32), 3-stage cp.async.
// smem rows padded to 40 bf16 (80 B) -> conflict-free fragment LDS.
// ---------------------------------------------------------------------------
#define BKG        32
#define SROW       40                    // bf16 elems per smem row (80 B)
#define TILE_ELEM  (128 * SROW)          // 5120 bf16 per tile
#define STAGE_ELEM (4 * TILE_ELEM)       // Ah, Al, Bh, Bl
#define NSTAGE     3
#define GEMM_SMEM  (NSTAGE * STAGE_ELEM * 2)   // bytes = 122880

__device__ __forceinline__ void load_stage(uint32_t s_base,   // smem byte addr of stage
                                           const __nv_bfloat16* Ah, const __nv_bfloat16* Al,
                                           const __nv_bfloat16* Bh, const __nv_bfloat16* Bl,
                                           int m0, int n0, int k0, int K, int tid) {
    // 128 rows x 4 chunks (16B) per tile; 512 chunks; 2 per thread per tile
#pragma unroll
    for (int p = 0; p < 2; p++) {
        int v = tid + p * 256;
        int row = v >> 2;
        int c = v & 3;
        uint32_t soff = (uint32_t)(row * (SROW * 2) + c * 16);
        cp_async16(s_base + soff,
                   (const char*)(Ah + (size_t)(m0 + row) * K + k0) + c * 16);
        cp_async16(s_base + TILE_ELEM * 2 + soff,
                   (const char*)(Al + (size_t)(m0 + row) * K + k0) + c * 16);
        cp_async16(s_base + 2 * TILE_ELEM * 2 + soff,
                   (const char*)(Bh + (size_t)(n0 + row) * K + k0) + c * 16);
        cp_async16(s_base + 3 * TILE_ELEM * 2 + soff,
                   (const char*)(Bl + (size_t)(n0 + row) * K + k0) + c * 16);
    }
}

__global__ __launch_bounds__(256, 1) void gemm_tc(const __nv_bfloat16* __restrict__ Ah,
                                                  const __nv_bfloat16* __restrict__ Al,
                                                  const __nv_bfloat16* __restrict__ Bh,
                                                  const __nv_bfloat16* __restrict__ Bl,
                                                  float* __restrict__ C,
                                                  int M, int N, int K) {
    extern __shared__ __nv_bfloat16 smem[];
    const uint32_t sbase = smem_u32(smem);

    const int tid = threadIdx.x;
    const int wid = tid >> 5;
    const int lane = tid & 31;
    const int g = lane >> 2;        // groupID 0..7
    const int t = lane & 3;         // thread-in-group
    const int m0 = blockIdx.y * 128;
    const int n0 = blockIdx.x * 128;
    const int wm = (wid >> 2) * 64;  // warp m offset in tile
    const int wn = (wid & 3) * 32;   // warp n offset in tile

    float acc[4][4][4];
#pragma unroll
    for (int mi = 0; mi < 4; mi++)
#pragma unroll
        for (int ni = 0; ni < 4; ni++)
#pragma unroll
            for (int r = 0; r < 4; r++) acc[mi][ni][r] = 0.f;

    const int NIT = K / BKG;

    // Prologue: stages 0..NSTAGE-2
#pragma unroll
    for (int s = 0; s < NSTAGE - 1; s++) {
        load_stage(sbase + s * STAGE_ELEM * 2, Ah, Al, Bh, Bl, m0, n0, s * BKG, K, tid);
        asm volatile("cp.async.commit_group;" ::: "memory");
    }

    for (int it = 0; it < NIT; it++) {
        // issue load of stage it+NSTAGE-1 (or empty group to keep counts uniform)
        if (it + NSTAGE - 1 < NIT) {
            int s = (it + NSTAGE - 1) % NSTAGE;
            load_stage(sbase + s * STAGE_ELEM * 2, Ah, Al, Bh, Bl,
                       m0, n0, (it + NSTAGE - 1) * BKG, K, tid);
        }
        asm volatile("cp.async.commit_group;" ::: "memory");
        asm volatile("cp.async.wait_group %0;" :: "n"(NSTAGE - 1) : "memory");
        __syncthreads();

        const __nv_bfloat16* sAh = smem + (it % NSTAGE) * STAGE_ELEM;
        const __nv_bfloat16* sAl = sAh + TILE_ELEM;
        const __nv_bfloat16* sBh = sAh + 2 * TILE_ELEM;
        const __nv_bfloat16* sBl = sAh + 3 * TILE_ELEM;

#pragma unroll
        for (int ks = 0; ks < 2; ks++) {
            const int kb = ks * 16;
            uint32_t ah[4][4], al[4][4], bh[4][2], bl[4][2];
#pragma unroll
            for (int mi = 0; mi < 4; mi++) {
                int r0 = wm + mi * 16 + g;
                int c0 = kb + 2 * t;
                ah[mi][0] = *(const uint32_t*)&sAh[r0 * SROW + c0];
                ah[mi][1] = *(const uint32_t*)&sAh[(r0 + 8) * SROW + c0];
                ah[mi][2] = *(const uint32_t*)&sAh[r0 * SROW + c0 + 8];
                ah[mi][3] = *(const uint32_t*)&sAh[(r0 + 8) * SROW + c0 + 8];
                al[mi][0] = *(const uint32_t*)&sAl[r0 * SROW + c0];
                al[mi][1] = *(const uint32_t*)&sAl[(r0 + 8) * SROW + c0];
                al[mi][2] = *(const uint32_t*)&sAl[r0 * SROW + c0 + 8];
                al[mi][3] = *(const uint32_t*)&sAl[(r0 + 8) * SROW + c0 + 8];
            }
#pragma unroll
            for (int ni = 0; ni < 4; ni++) {
                int r0 = wn + ni * 8 + g;
                int c0 = kb + 2 * t;
                bh[ni][0] = *(const uint32_t*)&sBh[r0 * SROW + c0];
                bh[ni][1] = *(const uint32_t*)&sBh[r0 * SROW + c0 + 8];
                bl[ni][0] = *(const uint32_t*)&sBl[r0 * SROW + c0];
                bl[ni][1] = *(const uint32_t*)&sBl[r0 * SROW + c0 + 8];
            }
#pragma unroll
            for (int mi = 0; mi < 4; mi++)
#pragma unroll
                for (int ni = 0; ni < 4; ni++) {
                    mma16816(acc[mi][ni], ah[mi], bh[ni]);   // Ah*Bh
                    mma16816(acc[mi][ni], ah[mi], bl[ni]);   // Ah*Bl
                    mma16816(acc[mi][ni], al[mi], bh[ni]);   // Al*Bh
                }
        }
        __syncthreads();
    }

    // Epilogue: write fp32 accumulators
#pragma unroll
    for (int mi = 0; mi < 4; mi++) {
        int row0 = m0 + wm + mi * 16 + g;
#pragma unroll
        for (int ni = 0; ni < 4; ni++) {
            int col = n0 + wn + ni * 8 + 2 * t;
            *(float2*)&C[(size_t)row0 * N + col] =
                make_float2(acc[mi][ni][0], acc[mi][ni][1]);
            *(float2*)&C[(size_t)(row0 + 8) * N + col] =
                make_float2(acc[mi][ni][2], acc[mi][ni][3]);
        }
    }
}

// ---------------------------------------------------------------------------
// Flash attention (causal), fp32 — unchanged from R1 (passed, rel_err 1e-6).
// ---------------------------------------------------------------------------
__global__ __launch_bounds__(256) void attn_kernel(const float* __restrict__ qkv,
                                                   float* __restrict__ y) {
    constexpr int BQ = 64, BKT = 64, DH = 64, LD = DH + 4;   // 68
    extern __shared__ float sm[];
    float* Qs = sm;
    float* Kt = Qs + BQ * LD;
    float* Vs = Kt + DH * LD;
    float* Ps = Vs + BKT * LD;

    const int tid = threadIdx.x;
    const int tx = tid & 15;
    const int ty = tid >> 4;
    const int qt = blockIdx.x;
    const int h  = blockIdx.y;
    const int b  = blockIdx.z;
    const int q0 = qt * BQ;
    const float scale = 0.125f;

    const size_t rowstride = 3 * D_MODEL;
    const float* qbase = qkv + (size_t)b * SEQ * rowstride + h * D_HEAD;
    const float* kbase = qbase + D_MODEL;
    const float* vbase = qbase + 2 * D_MODEL;

#pragma unroll
    for (int li = 0; li < 4; li++) {
        int vec = li * 256 + tid;
        int i = vec >> 4;
        int d = (vec & 15) * 4;
        float4 v = *(const float4*)&qbase[(size_t)(q0 + i) * rowstride + d];
        v.x *= scale; v.y *= scale; v.z *= scale; v.w *= scale;
        *(float4*)&Qs[i * LD + d] = v;
    }

    float acc[4][4];
    float mrow[4], lrow[4];
#pragma unroll
    for (int r = 0; r < 4; r++) {
        mrow[r] = -1e9f; lrow[r] = 0.f;
#pragma unroll
        for (int c = 0; c < 4; c++) acc[r][c] = 0.f;
    }

    const int ntiles = qt + 1;
    for (int kt = 0; kt < ntiles; kt++) {
        const int k0 = kt * BKT;
        __syncthreads();

#pragma unroll
        for (int li = 0; li < 4; li++) {
            int vec = li * 256 + tid;
            int j = vec >> 4;
            int d = (vec & 15) * 4;
            float4 kv = *(const float4*)&kbase[(size_t)(k0 + j) * rowstride + d];
            Kt[(d + 0) * LD + j] = kv.x;
            Kt[(d + 1) * LD + j] = kv.y;
            Kt[(d + 2) * LD + j] = kv.z;
            Kt[(d + 3) * LD + j] = kv.w;
            float4 vv = *(const float4*)&vbase[(size_t)(k0 + j) * rowstride + d];
            *(float4*)&Vs[j * LD + d] = vv;
        }
        __syncthreads();

        float s[4][4];
#pragma unroll
        for (int r = 0; r < 4; r++)
#pragma unroll
            for (int c = 0; c < 4; c++) s[r][c] = 0.f;

#pragma unroll 8
        for (int d = 0; d < DH; d++) {
            float a0 = Qs[(ty * 4 + 0) * LD + d];
            float a1 = Qs[(ty * 4 + 1) * LD + d];
            float a2 = Qs[(ty * 4 + 2) * LD + d];
            float a3 = Qs[(ty * 4 + 3) * LD + d];
            float4 k4 = *(const float4*)&Kt[d * LD + tx * 4];
            s[0][0] = fmaf(a0, k4.x, s[0][0]); s[0][1] = fmaf(a0, k4.y, s[0][1]);
            s[0][2] = fmaf(a0, k4.z, s[0][2]); s[0][3] = fmaf(a0, k4.w, s[0][3]);
            s[1][0] = fmaf(a1, k4.x, s[1][0]); s[1][1] = fmaf(a1, k4.y, s[1][1]);
            s[1][2] = fmaf(a1, k4.z, s[1][2]); s[1][3] = fmaf(a1, k4.w, s[1][3]);
            s[2][0] = fmaf(a2, k4.x, s[2][0]); s[2][1] = fmaf(a2, k4.y, s[2][1]);
            s[2][2] = fmaf(a2, k4.z, s[2][2]); s[2][3] = fmaf(a2, k4.w, s[2][3]);
            s[3][0] = fmaf(a3, k4.x, s[3][0]); s[3][1] = fmaf(a3, k4.y, s[3][1]);
            s[3][2] = fmaf(a3, k4.z, s[3][2]); s[3][3] = fmaf(a3, k4.w, s[3][3]);
        }

        if (kt == qt) {
#pragma unroll
            for (int r = 0; r < 4; r++) {
                int qr = q0 + ty * 4 + r;
#pragma unroll
                for (int c = 0; c < 4; c++) {
                    int kc = k0 + tx * 4 + c;
                    if (kc > qr) s[r][c] = -1e9f;
                }
            }
        }

#pragma unroll
        for (int r = 0; r < 4; r++) {
            float mx = fmaxf(fmaxf(s[r][0], s[r][1]), fmaxf(s[r][2], s[r][3]));
            mx = fmaxf(mx, __shfl_xor_sync(0xffffffffu, mx, 1));
            mx = fmaxf(mx, __shfl_xor_sync(0xffffffffu, mx, 2));
            mx = fmaxf(mx, __shfl_xor_sync(0xffffffffu, mx, 4));
            mx = fmaxf(mx, __shfl_xor_sync(0xffffffffu, mx, 8));
            float mnew = fmaxf(mrow[r], mx);
            float corr = __expf(mrow[r] - mnew);
            mrow[r] = mnew;
            float ls = 0.f;
#pragma unroll
            for (int c = 0; c < 4; c++) {
                float p = __expf(s[r][c] - mnew);
                s[r][c] = p;
                ls += p;
            }
            ls += __shfl_xor_sync(0xffffffffu, ls, 1);
            ls += __shfl_xor_sync(0xffffffffu, ls, 2);
            ls += __shfl_xor_sync(0xffffffffu, ls, 4);
            ls += __shfl_xor_sync(0xffffffffu, ls, 8);
            lrow[r] = lrow[r] * corr + ls;
#pragma unroll
            for (int c = 0; c < 4; c++) acc[r][c] *= corr;
            *(float4*)&Ps[(ty * 4 + r) * LD + tx * 4] =
                make_float4(s[r][0], s[r][1], s[r][2], s[r][3]);
        }
        __syncthreads();

#pragma unroll 8
        for (int j = 0; j < BKT; j++) {
            float p0 = Ps[(ty * 4 + 0) * LD + j];
            float p1 = Ps[(ty * 4 + 1) * LD + j];
            float p2 = Ps[(ty * 4 + 2) * LD + j];
            float p3 = Ps[(ty * 4 + 3) * LD + j];
            float4 v4 = *(const float4*)&Vs[j * LD + tx * 4];
            acc[0][0] = fmaf(p0, v4.x, acc[0][0]); acc[0][1] = fmaf(p0, v4.y, acc[0][1]);
            acc[0][2] = fmaf(p0, v4.z, acc[0][2]); acc[0][3] = fmaf(p0, v4.w, acc[0][3]);
            acc[1][0] = fmaf(p1, v4.x, acc[1][0]); acc[1][1] = fmaf(p1, v4.y, acc[1][1]);
            acc[1][2] = fmaf(p1, v4.z, acc[1][2]); acc[1][3] = fmaf(p1, v4.w, acc[1][3]);
            acc[2][0] = fmaf(p2, v4.x, acc[2][0]); acc[2][1] = fmaf(p2, v4.y, acc[2][1]);
            acc[2][2] = fmaf(p2, v4.z, acc[2][2]); acc[2][3] = fmaf(p2, v4.w, acc[2][3]);
            acc[3][0] = fmaf(p3, v4.x, acc[3][0]); acc[3][1] = fmaf(p3, v4.y, acc[3][1]);
            acc[3][2] = fmaf(p3, v4.z, acc[3][2]); acc[3][3] = fmaf(p3, v4.w, acc[3][3]);
        }
    }

#pragma unroll
    for (int r = 0; r < 4; r++) {
        float inv = 1.f / lrow[r];
        float4 o = make_float4(acc[r][0] * inv, acc[r][1] * inv,
                               acc[r][2] * inv, acc[r][3] * inv);
        size_t t = (size_t)b * SEQ + q0 + ty * 4 + r;
        *(float4*)&y[t * D_MODEL + h * D_HEAD + tx * 4] = o;
    }
}

// ---------------------------------------------------------------------------
extern "C" void kernel_launch(void* const* d_in, const int* in_sizes, int n_in,
                              void* d_out, int out_size) {
    const float* x    = (const float*)d_in[0];
    const float* Wqkv = (const float*)d_in[1];
    const float* Wout = (const float*)d_in[2];
    float* out = (float*)d_out;

    float *qkv, *y;
    cudaGetSymbolAddress((void**)&qkv, g_qkv);
    cudaGetSymbolAddress((void**)&y, g_y);
    __nv_bfloat16 *xh, *xl, *w1h, *w1l, *w2h, *w2l, *yh, *yl;
    cudaGetSymbolAddress((void**)&xh, g_xh);
    cudaGetSymbolAddress((void**)&xl, g_xl);
    cudaGetSymbolAddress((void**)&w1h, g_w1h);
    cudaGetSymbolAddress((void**)&w1l, g_w1l);
    cudaGetSymbolAddress((void**)&w2h, g_w2h);
    cudaGetSymbolAddress((void**)&w2l, g_w2l);
    cudaGetSymbolAddress((void**)&yh, g_yh);
    cudaGetSymbolAddress((void**)&yl, g_yl);

    cudaFuncSetAttribute(gemm_tc, cudaFuncAttributeMaxDynamicSharedMemorySize, GEMM_SMEM);

    // Splits
    {
        int n4 = ROWS * D_MODEL / 4;
        split_bf16<<<(n4 + 255) / 256, 256>>>(x, xh, xl, n4);
        int w1n4 = 3 * D_MODEL * D_MODEL / 4;
        split_bf16<<<(w1n4 + 255) / 256, 256>>>(Wqkv, w1h, w1l, w1n4);
        int w2n4 = D_MODEL * D_MODEL / 4;
        split_bf16<<<(w2n4 + 255) / 256, 256>>>(Wout, w2h, w2l, w2n4);
    }

    // 1) QKV projection: [4096,1024] x [3072,1024]^T
    gemm_tc<<<dim3(3 * D_MODEL / 128, ROWS / 128), 256, GEMM_SMEM>>>(
        xh, xl, w1h, w1l, qkv, ROWS, 3 * D_MODEL, D_MODEL);

    // 2) Causal flash attention -> y [4096,1024] (fp32)
    int shmem = 4 * 64 * 68 * (int)sizeof(float);
    cudaFuncSetAttribute(attn_kernel, cudaFuncAttributeMaxDynamicSharedMemorySize, shmem);
    attn_kernel<<<dim3(SEQ / 64, NUM_HEADS, BATCH), 256, shmem>>>(qkv, y);

    // 3) Split y, then output projection
    {
        int n4 = ROWS * D_MODEL / 4;
        split_bf16<<<(n4 + 255) / 256, 256>>>(y, yh, yl, n4);
    }
    gemm_tc<<<dim3(D_MODEL / 128, ROWS / 128), 256, GEMM_SMEM>>>(
        yh, yl, w2h, w2l, out, ROWS, D_MODEL, D_MODEL);
}

// round 4
// speedup vs baseline: 2.4323x; 1.6936x over previous
#include <cuda_runtime.h>
#include <cuda_bf16.h>
#include <cstdint>

#define D_MODEL   1024
#define NUM_HEADS 16
#define D_HEAD    64
#define BATCH     2
#define SEQ       2048
#define ROWS      (BATCH * SEQ)   // 4096

// ---------------------------------------------------------------------------
// Scratch (alloc-free rule: __device__ globals)
// ---------------------------------------------------------------------------
__device__ float g_qkv[(size_t)ROWS * 3 * D_MODEL];   // fp32 QKV
__device__ float g_y[(size_t)ROWS * D_MODEL];         // fp32 attention out

__device__ __nv_bfloat16 g_xh[(size_t)ROWS * D_MODEL];
__device__ __nv_bfloat16 g_xl[(size_t)ROWS * D_MODEL];
__device__ __nv_bfloat16 g_w1h[(size_t)3 * D_MODEL * D_MODEL];
__device__ __nv_bfloat16 g_w1l[(size_t)3 * D_MODEL * D_MODEL];
__device__ __nv_bfloat16 g_w2h[(size_t)D_MODEL * D_MODEL];
__device__ __nv_bfloat16 g_w2l[(size_t)D_MODEL * D_MODEL];
__device__ __nv_bfloat16 g_yh[(size_t)ROWS * D_MODEL];
__device__ __nv_bfloat16 g_yl[(size_t)ROWS * D_MODEL];

// ---------------------------------------------------------------------------
__device__ __forceinline__ uint32_t smem_u32(const void* p) {
    uint32_t a;
    asm("{ .reg .u64 t; cvta.to.shared.u64 t, %1; cvt.u32.u64 %0, t; }"
        : "=r"(a) : "l"(p));
    return a;
}

__device__ __forceinline__ void cp_async16(uint32_t dst, const void* src) {
    asm volatile("cp.async.cg.shared.global [%0], [%1], 16;" :: "r"(dst), "l"(src));
}

__device__ __forceinline__ void mma16816(float* c, const uint32_t* a, const uint32_t* b) {
    asm volatile(
        "mma.sync.aligned.m16n8k16.row.col.f32.bf16.bf16.f32 "
        "{%0,%1,%2,%3}, {%4,%5,%6,%7}, {%8,%9}, {%0,%1,%2,%3};"
        : "+f"(c[0]), "+f"(c[1]), "+f"(c[2]), "+f"(c[3])
        : "r"(a[0]), "r"(a[1]), "r"(a[2]), "r"(a[3]), "r"(b[0]), "r"(b[1]));
}

__device__ __forceinline__ void ldsm_x4(uint32_t* r, uint32_t addr) {
    asm volatile("ldmatrix.sync.aligned.m8n8.x4.shared.b16 {%0,%1,%2,%3}, [%4];"
        : "=r"(r[0]), "=r"(r[1]), "=r"(r[2]), "=r"(r[3]) : "r"(addr));
}

__device__ __forceinline__ void ldsm_x4_t(uint32_t* r, uint32_t addr) {
    asm volatile("ldmatrix.sync.aligned.m8n8.x4.trans.shared.b16 {%0,%1,%2,%3}, [%4];"
        : "=r"(r[0]), "=r"(r[1]), "=r"(r[2]), "=r"(r[3]) : "r"(addr));
}

// pack two fp32 -> bf16x2 hi word + exact residual lo word (lo half = x, hi half = y)
__device__ __forceinline__ void pack_hilo(float x, float y, uint32_t& hp, uint32_t& lp) {
    asm("cvt.rn.bf16x2.f32 %0, %1, %2;" : "=r"(hp) : "f"(y), "f"(x));
    float xh = __uint_as_float(hp << 16);
    float yh = __uint_as_float(hp & 0xffff0000u);
    float xl = x - xh;
    float yl = y - yh;
    asm("cvt.rn.bf16x2.f32 %0, %1, %2;" : "=r"(lp) : "f"(yl), "f"(xl));
}

// split a float4 into hi/lo bf16 quads and store (8 B each) to smem
__device__ __forceinline__ void split_store4(uint32_t sh, uint32_t sl, float4 v) {
    uint32_t h0, h1, l0, l1;
    pack_hilo(v.x, v.y, h0, l0);
    pack_hilo(v.z, v.w, h1, l1);
    asm volatile("st.shared.v2.u32 [%0], {%1,%2};" :: "r"(sh), "r"(h0), "r"(h1));
    asm volatile("st.shared.v2.u32 [%0], {%1,%2};" :: "r"(sl), "r"(l0), "r"(l1));
}

// ---------------------------------------------------------------------------
// Split fp32 -> bf16 hi/lo (global)
// ---------------------------------------------------------------------------
__global__ __launch_bounds__(256) void split_bf16(const float* __restrict__ src,
                                                  __nv_bfloat16* __restrict__ hi,
                                                  __nv_bfloat16* __restrict__ lo,
                                                  int n4) {
    int i = blockIdx.x * blockDim.x + threadIdx.x;
    if (i >= n4) return;
    float4 v = ((const float4*)src)[i];
    float f[4] = {v.x, v.y, v.z, v.w};
    __nv_bfloat16 h[4], l[4];
#pragma unroll
    for (int j = 0; j < 4; j++) {
        h[j] = __float2bfloat16(f[j]);
        l[j] = __float2bfloat16(f[j] - __bfloat162float(h[j]));
    }
    ((uint2*)hi)[i] = *(uint2*)h;
    ((uint2*)lo)[i] = *(uint2*)l;
}

// ---------------------------------------------------------------------------
// Tensor-core GEMM NT via mma.sync (bf16, 3-term hi/lo) — unchanged from R3.
// ---------------------------------------------------------------------------
#define BKG        32
#define SROW       40
#define TILE_ELEM  (128 * SROW)
#define STAGE_ELEM (4 * TILE_ELEM)
#define NSTAGE     3
#define GEMM_SMEM  (NSTAGE * STAGE_ELEM * 2)

__device__ __forceinline__ void load_stage(uint32_t s_base,
                                           const __nv_bfloat16* Ah, const __nv_bfloat16* Al,
                                           const __nv_bfloat16* Bh, const __nv_bfloat16* Bl,
                                           int m0, int n0, int k0, int K, int tid) {
#pragma unroll
    for (int p = 0; p < 2; p++) {
        int v = tid + p * 256;
        int row = v >> 2;
        int c = v & 3;
        uint32_t soff = (uint32_t)(row * (SROW * 2) + c * 16);
        cp_async16(s_base + soff,
                   (const char*)(Ah + (size_t)(m0 + row) * K + k0) + c * 16);
        cp_async16(s_base + TILE_ELEM * 2 + soff,
                   (const char*)(Al + (size_t)(m0 + row) * K + k0) + c * 16);
        cp_async16(s_base + 2 * TILE_ELEM * 2 + soff,
                   (const char*)(Bh + (size_t)(n0 + row) * K + k0) + c * 16);
        cp_async16(s_base + 3 * TILE_ELEM * 2 + soff,
                   (const char*)(Bl + (size_t)(n0 + row) * K + k0) + c * 16);
    }
}

__global__ __launch_bounds__(256, 1) void gemm_tc(const __nv_bfloat16* __restrict__ Ah,
                                                  const __nv_bfloat16* __restrict__ Al,
                                                  const __nv_bfloat16* __restrict__ Bh,
                                                  const __nv_bfloat16* __restrict__ Bl,
                                                  float* __restrict__ C,
                                                  int M, int N, int K) {
    extern __shared__ __nv_bfloat16 smem[];
    const uint32_t sbase = smem_u32(smem);

    const int tid = threadIdx.x;
    const int wid = tid >> 5;
    const int lane = tid & 31;
    const int g = lane >> 2;
    const int t = lane & 3;
    const int m0 = blockIdx.y * 128;
    const int n0 = blockIdx.x * 128;
    const int wm = (wid >> 2) * 64;
    const int wn = (wid & 3) * 32;

    float acc[4][4][4];
#pragma unroll
    for (int mi = 0; mi < 4; mi++)
#pragma unroll
        for (int ni = 0; ni < 4; ni++)
#pragma unroll
            for (int r = 0; r < 4; r++) acc[mi][ni][r] = 0.f;

    const int NIT = K / BKG;

#pragma unroll
    for (int s = 0; s < NSTAGE - 1; s++) {
        load_stage(sbase + s * STAGE_ELEM * 2, Ah, Al, Bh, Bl, m0, n0, s * BKG, K, tid);
        asm volatile("cp.async.commit_group;" ::: "memory");
    }

    for (int it = 0; it < NIT; it++) {
        if (it + NSTAGE - 1 < NIT) {
            int s = (it + NSTAGE - 1) % NSTAGE;
            load_stage(sbase + s * STAGE_ELEM * 2, Ah, Al, Bh, Bl,
                       m0, n0, (it + NSTAGE - 1) * BKG, K, tid);
        }
        asm volatile("cp.async.commit_group;" ::: "memory");
        asm volatile("cp.async.wait_group %0;" :: "n"(NSTAGE - 1) : "memory");
        __syncthreads();

        const __nv_bfloat16* sAh = smem + (it % NSTAGE) * STAGE_ELEM;
        const __nv_bfloat16* sAl = sAh + TILE_ELEM;
        const __nv_bfloat16* sBh = sAh + 2 * TILE_ELEM;
        const __nv_bfloat16* sBl = sAh + 3 * TILE_ELEM;

#pragma unroll
        for (int ks = 0; ks < 2; ks++) {
            const int kb = ks * 16;
            uint32_t ah[4][4], al[4][4], bh[4][2], bl[4][2];
#pragma unroll
            for (int mi = 0; mi < 4; mi++) {
                int r0 = wm + mi * 16 + g;
                int c0 = kb + 2 * t;
                ah[mi][0] = *(const uint32_t*)&sAh[r0 * SROW + c0];
                ah[mi][1] = *(const uint32_t*)&sAh[(r0 + 8) * SROW + c0];
                ah[mi][2] = *(const uint32_t*)&sAh[r0 * SROW + c0 + 8];
                ah[mi][3] = *(const uint32_t*)&sAh[(r0 + 8) * SROW + c0 + 8];
                al[mi][0] = *(const uint32_t*)&sAl[r0 * SROW + c0];
                al[mi][1] = *(const uint32_t*)&sAl[(r0 + 8) * SROW + c0];
                al[mi][2] = *(const uint32_t*)&sAl[r0 * SROW + c0 + 8];
                al[mi][3] = *(const uint32_t*)&sAl[(r0 + 8) * SROW + c0 + 8];
            }
#pragma unroll
            for (int ni = 0; ni < 4; ni++) {
                int r0 = wn + ni * 8 + g;
                int c0 = kb + 2 * t;
                bh[ni][0] = *(const uint32_t*)&sBh[r0 * SROW + c0];
                bh[ni][1] = *(const uint32_t*)&sBh[r0 * SROW + c0 + 8];
                bl[ni][0] = *(const uint32_t*)&sBl[r0 * SROW + c0];
                bl[ni][1] = *(const uint32_t*)&sBl[r0 * SROW + c0 + 8];
            }
#pragma unroll
            for (int mi = 0; mi < 4; mi++)
#pragma unroll
                for (int ni = 0; ni < 4; ni++) {
                    mma16816(acc[mi][ni], ah[mi], bh[ni]);
                    mma16816(acc[mi][ni], ah[mi], bl[ni]);
                    mma16816(acc[mi][ni], al[mi], bh[ni]);
                }
        }
        __syncthreads();
    }

#pragma unroll
    for (int mi = 0; mi < 4; mi++) {
        int row0 = m0 + wm + mi * 16 + g;
#pragma unroll
        for (int ni = 0; ni < 4; ni++) {
            int col = n0 + wn + ni * 8 + 2 * t;
            *(float2*)&C[(size_t)row0 * N + col] =
                make_float2(acc[mi][ni][0], acc[mi][ni][1]);
            *(float2*)&C[(size_t)(row0 + 8) * N + col] =
                make_float2(acc[mi][ni][2], acc[mi][ni][3]);
        }
    }
}

// ---------------------------------------------------------------------------
// Tensor-core causal flash attention. BQ=128, BK=64, Dh=64, 256 threads.
// Q/K/V in smem as bf16 hi/lo (row stride 72 elems = 144 B), fragments via
// ldmatrix; P kept register-resident; 3-term hi/lo compensation on both MMAs.
// smem: QH 18432 | QL 18432 | KH 9216 | KL 9216 | VH 9216 | VL 9216 = 73728 B
// ---------------------------------------------------------------------------
#define AT_SMEM 73728

__global__ __launch_bounds__(256) void attn_tc(const float* __restrict__ qkv,
                                               float* __restrict__ y) {
    extern __shared__ __nv_bfloat16 asmem[];
    const uint32_t sb = smem_u32(asmem);
    const uint32_t QH = sb, QL = sb + 18432, KH = sb + 36864, KL = sb + 46080,
                   VH = sb + 55296, VL = sb + 64512;

    const int tid = threadIdx.x;
    const int wid = tid >> 5;
    const int lane = tid & 31;
    const int g = lane >> 2, t = lane & 3;
    const int qt = blockIdx.x, h = blockIdx.y, b = blockIdx.z;
    const int q0 = qt * 128;

    const size_t rowstride = 3 * D_MODEL;
    const float* qbase = qkv + (size_t)b * SEQ * rowstride + h * D_HEAD;
    const float* kbase = qbase + D_MODEL;
    const float* vbase = qbase + 2 * D_MODEL;

    // ldmatrix per-lane addressing components
    const int lrow  = (lane & 7) + 8 * ((lane >> 3) & 1);   // Q (A-frag), V (trans)
    const int lcol8 = 8 * (lane >> 4);
    const int lrowK = (lane & 7) + 8 * (lane >> 4);          // K (B-frag, non-trans)
    const int lcol8K = 8 * ((lane >> 3) & 1);

    // ---- load + split Q (pre-scaled by 1/sqrt(Dh)) ----
    {
        const float scale = 0.125f;
#pragma unroll
        for (int p = 0; p < 8; p++) {
            int v = tid + p * 256;
            int row = v >> 4, c = v & 15;
            float4 q4 = *(const float4*)&qbase[(size_t)(q0 + row) * rowstride + c * 4];
            q4.x *= scale; q4.y *= scale; q4.z *= scale; q4.w *= scale;
            split_store4(QH + row * 144 + c * 8, QL + row * 144 + c * 8, q4);
        }
    }

    float m_[2] = {-1e30f, -1e30f};
    float l_[2] = {0.f, 0.f};
    float o[8][4];
#pragma unroll
    for (int nt = 0; nt < 8; nt++)
#pragma unroll
        for (int c = 0; c < 4; c++) o[nt][c] = 0.f;

    const int ntiles = 2 * qt + 2;
    for (int kt = 0; kt < ntiles; kt++) {
        __syncthreads();   // previous iteration's MMAs done with K/V smem (covers Q store at kt=0)

        // ---- load + split K, V tiles (64 rows x 64 cols fp32) ----
#pragma unroll
        for (int p = 0; p < 4; p++) {
            int v = tid + p * 256;
            int j = v >> 4, c = v & 15;
            float4 k4 = *(const float4*)&kbase[(size_t)(kt * 64 + j) * rowstride + c * 4];
            split_store4(KH + j * 144 + c * 8, KL + j * 144 + c * 8, k4);
            float4 v4 = *(const float4*)&vbase[(size_t)(kt * 64 + j) * rowstride + c * 4];
            split_store4(VH + j * 144 + c * 8, VL + j * 144 + c * 8, v4);
        }
        __syncthreads();

        // ---- S = Q K^T (128x64 strip per warp: 16x64) ----
        float s[8][4];
#pragma unroll
        for (int nt = 0; nt < 8; nt++)
#pragma unroll
            for (int c = 0; c < 4; c++) s[nt][c] = 0.f;

#pragma unroll
        for (int ks = 0; ks < 4; ks++) {
            uint32_t ah[4], al[4];
            uint32_t qoff = (uint32_t)((wid * 16 + lrow) * 144 + (ks * 16 + lcol8) * 2);
            ldsm_x4(ah, QH + qoff);
            ldsm_x4(al, QL + qoff);
#pragma unroll
            for (int ntp = 0; ntp < 4; ntp++) {
                uint32_t bh[4], bl[4];
                uint32_t koff = (uint32_t)((ntp * 16 + lrowK) * 144 + (ks * 16 + lcol8K) * 2);
                ldsm_x4(bh, KH + koff);
                ldsm_x4(bl, KL + koff);
                mma16816(s[2 * ntp],     ah, bh);
                mma16816(s[2 * ntp],     ah, bl);
                mma16816(s[2 * ntp],     al, bh);
                mma16816(s[2 * ntp + 1], ah, bh + 2);
                mma16816(s[2 * ntp + 1], ah, bl + 2);
                mma16816(s[2 * ntp + 1], al, bh + 2);
            }
        }

        // ---- causal mask (only the two diagonal-adjacent tiles) ----
        if (kt >= 2 * qt) {
#pragma unroll
            for (int nt = 0; nt < 8; nt++)
#pragma unroll
                for (int c = 0; c < 4; c++) {
                    int row = q0 + wid * 16 + g + (c >> 1) * 8;
                    int col = kt * 64 + nt * 8 + 2 * t + (c & 1);
                    if (col > row) s[nt][c] = -1e30f;
                }
        }

        // ---- online softmax (rows g and g+8; reduce over the 4 t-lanes) ----
#pragma unroll
        for (int r = 0; r < 2; r++) {
            float mx = -1e30f;
#pragma unroll
            for (int nt = 0; nt < 8; nt++)
                mx = fmaxf(mx, fmaxf(s[nt][2 * r], s[nt][2 * r + 1]));
            mx = fmaxf(mx, __shfl_xor_sync(0xffffffffu, mx, 1));
            mx = fmaxf(mx, __shfl_xor_sync(0xffffffffu, mx, 2));
            float mnew = fmaxf(m_[r], mx);
            float corr = __expf(m_[r] - mnew);
            m_[r] = mnew;
            float ls = 0.f;
#pragma unroll
            for (int nt = 0; nt < 8; nt++) {
                float p0 = __expf(s[nt][2 * r] - mnew);
                float p1 = __expf(s[nt][2 * r + 1] - mnew);
                s[nt][2 * r] = p0;
                s[nt][2 * r + 1] = p1;
                ls += p0 + p1;
            }
            ls += __shfl_xor_sync(0xffffffffu, ls, 1);
            ls += __shfl_xor_sync(0xffffffffu, ls, 2);
            l_[r] = l_[r] * corr + ls;
#pragma unroll
            for (int nt = 0; nt < 8; nt++) {
                o[nt][2 * r] *= corr;
                o[nt][2 * r + 1] *= corr;
            }
        }

        // ---- O += P V (P register-resident, hi/lo split) ----
#pragma unroll
        for (int kc = 0; kc < 4; kc++) {
            uint32_t ah[4], al[4];
            pack_hilo(s[2 * kc][0],     s[2 * kc][1],     ah[0], al[0]);
            pack_hilo(s[2 * kc][2],     s[2 * kc][3],     ah[1], al[1]);
            pack_hilo(s[2 * kc + 1][0], s[2 * kc + 1][1], ah[2], al[2]);
            pack_hilo(s[2 * kc + 1][2], s[2 * kc + 1][3], ah[3], al[3]);
#pragma unroll
            for (int ntp = 0; ntp < 4; ntp++) {
                uint32_t bh[4], bl[4];
                uint32_t voff = (uint32_t)((kc * 16 + lrow) * 144 + (ntp * 16 + lcol8) * 2);
                ldsm_x4_t(bh, VH + voff);
                ldsm_x4_t(bl, VL + voff);
                mma16816(o[2 * ntp],     ah, bh);
                mma16816(o[2 * ntp],     ah, bl);
                mma16816(o[2 * ntp],     al, bh);
                mma16816(o[2 * ntp + 1], ah, bh + 2);
                mma16816(o[2 * ntp + 1], ah, bl + 2);
                mma16816(o[2 * ntp + 1], al, bh + 2);
            }
        }
    }

    // ---- epilogue: normalize + write y[B,T,D_MODEL] ----
    {
        float inv0 = 1.f / l_[0];
        float inv1 = 1.f / l_[1];
        int row0 = q0 + wid * 16 + g;
        size_t t0 = (size_t)b * SEQ + row0;
#pragma unroll
        for (int nt = 0; nt < 8; nt++) {
            int col = h * D_HEAD + nt * 8 + 2 * t;
            *(float2*)&y[t0 * D_MODEL + col] =
                make_float2(o[nt][0] * inv0, o[nt][1] * inv0);
            *(float2*)&y[(t0 + 8) * D_MODEL + col] =
                make_float2(o[nt][2] * inv1, o[nt][3] * inv1);
        }
    }
}

// ---------------------------------------------------------------------------
extern "C" void kernel_launch(void* const* d_in, const int* in_sizes, int n_in,
                              void* d_out, int out_size) {
    const float* x    = (const float*)d_in[0];
    const float* Wqkv = (const float*)d_in[1];
    const float* Wout = (const float*)d_in[2];
    float* out = (float*)d_out;

    float *qkv, *y;
    cudaGetSymbolAddress((void**)&qkv, g_qkv);
    cudaGetSymbolAddress((void**)&y, g_y);
    __nv_bfloat16 *xh, *xl, *w1h, *w1l, *w2h, *w2l, *yh, *yl;
    cudaGetSymbolAddress((void**)&xh, g_xh);
    cudaGetSymbolAddress((void**)&xl, g_xl);
    cudaGetSymbolAddress((void**)&w1h, g_w1h);
    cudaGetSymbolAddress((void**)&w1l, g_w1l);
    cudaGetSymbolAddress((void**)&w2h, g_w2h);
    cudaGetSymbolAddress((void**)&w2l, g_w2l);
    cudaGetSymbolAddress((void**)&yh, g_yh);
    cudaGetSymbolAddress((void**)&yl, g_yl);

    cudaFuncSetAttribute(gemm_tc, cudaFuncAttributeMaxDynamicSharedMemorySize, GEMM_SMEM);
    cudaFuncSetAttribute(attn_tc, cudaFuncAttributeMaxDynamicSharedMemorySize, AT_SMEM);

    // Splits
    {
        int n4 = ROWS * D_MODEL / 4;
        split_bf16<<<(n4 + 255) / 256, 256>>>(x, xh, xl, n4);
        int w1n4 = 3 * D_MODEL * D_MODEL / 4;
        split_bf16<<<(w1n4 + 255) / 256, 256>>>(Wqkv, w1h, w1l, w1n4);
        int w2n4 = D_MODEL * D_MODEL / 4;
        split_bf16<<<(w2n4 + 255) / 256, 256>>>(Wout, w2h, w2l, w2n4);
    }

    // 1) QKV projection: [4096,1024] x [3072,1024]^T
    gemm_tc<<<dim3(3 * D_MODEL / 128, ROWS / 128), 256, GEMM_SMEM>>>(
        xh, xl, w1h, w1l, qkv, ROWS, 3 * D_MODEL, D_MODEL);

    // 2) Tensor-core causal flash attention -> y [4096,1024] (fp32)
    attn_tc<<<dim3(SEQ / 128, NUM_HEADS, BATCH), 256, AT_SMEM>>>(qkv, y);

    // 3) Split y, then output projection
    {
        int n4 = ROWS * D_MODEL / 4;
        split_bf16<<<(n4 + 255) / 256, 256>>>(y, yh, yl, n4);
    }
    gemm_tc<<<dim3(D_MODEL / 128, ROWS / 128), 256, GEMM_SMEM>>>(
        yh, yl, w2h, w2l, out, ROWS, D_MODEL, D_MODEL);
}

// round 5
// speedup vs baseline: 2.7397x; 1.1264x over previous
#include <cuda_runtime.h>
#include <cuda_bf16.h>
#include <cstdint>

#define D_MODEL   1024
#define NUM_HEADS 16
#define D_HEAD    64
#define BATCH     2
#define SEQ       2048
#define ROWS      (BATCH * SEQ)   // 4096

// ---------------------------------------------------------------------------
// Scratch (alloc-free rule: __device__ globals)
// ---------------------------------------------------------------------------
__device__ float g_qkv[(size_t)ROWS * 3 * D_MODEL];   // fp32 QKV

__device__ __nv_bfloat16 g_xh[(size_t)ROWS * D_MODEL];
__device__ __nv_bfloat16 g_xl[(size_t)ROWS * D_MODEL];
__device__ __nv_bfloat16 g_w1h[(size_t)3 * D_MODEL * D_MODEL];
__device__ __nv_bfloat16 g_w1l[(size_t)3 * D_MODEL * D_MODEL];
__device__ __nv_bfloat16 g_w2h[(size_t)D_MODEL * D_MODEL];
__device__ __nv_bfloat16 g_w2l[(size_t)D_MODEL * D_MODEL];
__device__ __nv_bfloat16 g_yh[(size_t)ROWS * D_MODEL];
__device__ __nv_bfloat16 g_yl[(size_t)ROWS * D_MODEL];

// ---------------------------------------------------------------------------
__device__ __forceinline__ uint32_t smem_u32(const void* p) {
    uint32_t a;
    asm("{ .reg .u64 t; cvta.to.shared.u64 t, %1; cvt.u32.u64 %0, t; }"
        : "=r"(a) : "l"(p));
    return a;
}

__device__ __forceinline__ void cp_async16(uint32_t dst, const void* src) {
    asm volatile("cp.async.cg.shared.global [%0], [%1], 16;" :: "r"(dst), "l"(src));
}

__device__ __forceinline__ void mma16816(float* c, const uint32_t* a, const uint32_t* b) {
    asm volatile(
        "mma.sync.aligned.m16n8k16.row.col.f32.bf16.bf16.f32 "
        "{%0,%1,%2,%3}, {%4,%5,%6,%7}, {%8,%9}, {%0,%1,%2,%3};"
        : "+f"(c[0]), "+f"(c[1]), "+f"(c[2]), "+f"(c[3])
        : "r"(a[0]), "r"(a[1]), "r"(a[2]), "r"(a[3]), "r"(b[0]), "r"(b[1]));
}

__device__ __forceinline__ void ldsm_x4(uint32_t* r, uint32_t addr) {
    asm volatile("ldmatrix.sync.aligned.m8n8.x4.shared.b16 {%0,%1,%2,%3}, [%4];"
        : "=r"(r[0]), "=r"(r[1]), "=r"(r[2]), "=r"(r[3]) : "r"(addr));
}

__device__ __forceinline__ void ldsm_x4_t(uint32_t* r, uint32_t addr) {
    asm volatile("ldmatrix.sync.aligned.m8n8.x4.trans.shared.b16 {%0,%1,%2,%3}, [%4];"
        : "=r"(r[0]), "=r"(r[1]), "=r"(r[2]), "=r"(r[3]) : "r"(addr));
}

// pack two fp32 -> bf16x2 hi word + exact residual lo word (lo half = x, hi half = y)
__device__ __forceinline__ void pack_hilo(float x, float y, uint32_t& hp, uint32_t& lp) {
    asm("cvt.rn.bf16x2.f32 %0, %1, %2;" : "=r"(hp) : "f"(y), "f"(x));
    float xh = __uint_as_float(hp << 16);
    float yh = __uint_as_float(hp & 0xffff0000u);
    float xl = x - xh;
    float yl = y - yh;
    asm("cvt.rn.bf16x2.f32 %0, %1, %2;" : "=r"(lp) : "f"(yl), "f"(xl));
}

__device__ __forceinline__ void split_store4(uint32_t sh, uint32_t sl, float4 v) {
    uint32_t h0, h1, l0, l1;
    pack_hilo(v.x, v.y, h0, l0);
    pack_hilo(v.z, v.w, h1, l1);
    asm volatile("st.shared.v2.u32 [%0], {%1,%2};" :: "r"(sh), "r"(h0), "r"(h1));
    asm volatile("st.shared.v2.u32 [%0], {%1,%2};" :: "r"(sl), "r"(l0), "r"(l1));
}

// ---------------------------------------------------------------------------
// Split fp32 -> bf16 hi/lo; elements with index < scale4_until*4 get *0.125
// (exact: power of two) — used to fold the attention scale into Wqkv Q-rows.
// ---------------------------------------------------------------------------
__global__ __launch_bounds__(256) void split_bf16(const float* __restrict__ src,
                                                  __nv_bfloat16* __restrict__ hi,
                                                  __nv_bfloat16* __restrict__ lo,
                                                  int n4, int scale4_until) {
    int i = blockIdx.x * blockDim.x + threadIdx.x;
    if (i >= n4) return;
    float sc = (i < scale4_until) ? 0.125f : 1.0f;
    float4 v = ((const float4*)src)[i];
    float f[4] = {v.x * sc, v.y * sc, v.z * sc, v.w * sc};
    __nv_bfloat16 h[4], l[4];
#pragma unroll
    for (int j = 0; j < 4; j++) {
        h[j] = __float2bfloat16(f[j]);
        l[j] = __float2bfloat16(f[j] - __bfloat162float(h[j]));
    }
    ((uint2*)hi)[i] = *(uint2*)h;
    ((uint2*)lo)[i] = *(uint2*)l;
}

// ---------------------------------------------------------------------------
// Tensor-core GEMM NT via mma.sync (bf16, 3-term hi/lo):
//   C[m,n] = sum_k A[m,k]*B[n,k]
// Block 128x128, BK=32, 8 warps (warp tile 64x32), 2-stage cp.async,
// ldmatrix fragment loads, 2 CTAs/SM.
// ---------------------------------------------------------------------------
#define BKG        32
#define SROW       40                    // bf16 elems per smem row (80 B)
#define TILE_ELEM  (128 * SROW)
#define STAGE_ELEM (4 * TILE_ELEM)       // Ah, Al, Bh, Bl
#define NSTAGE     2
#define GEMM_SMEM  (NSTAGE * STAGE_ELEM * 2)   // 81920 B

__device__ __forceinline__ void load_stage(uint32_t s_base,
                                           const __nv_bfloat16* Ah, const __nv_bfloat16* Al,
                                           const __nv_bfloat16* Bh, const __nv_bfloat16* Bl,
                                           int m0, int n0, int k0, int K, int tid) {
#pragma unroll
    for (int p = 0; p < 2; p++) {
        int v = tid + p * 256;
        int row = v >> 2;
        int c = v & 3;
        uint32_t soff = (uint32_t)(row * (SROW * 2) + c * 16);
        cp_async16(s_base + soff,
                   (const char*)(Ah + (size_t)(m0 + row) * K + k0) + c * 16);
        cp_async16(s_base + TILE_ELEM * 2 + soff,
                   (const char*)(Al + (size_t)(m0 + row) * K + k0) + c * 16);
        cp_async16(s_base + 2 * TILE_ELEM * 2 + soff,
                   (const char*)(Bh + (size_t)(n0 + row) * K + k0) + c * 16);
        cp_async16(s_base + 3 * TILE_ELEM * 2 + soff,
                   (const char*)(Bl + (size_t)(n0 + row) * K + k0) + c * 16);
    }
}

__global__ __launch_bounds__(256, 2) void gemm_tc(const __nv_bfloat16* __restrict__ Ah,
                                                  const __nv_bfloat16* __restrict__ Al,
                                                  const __nv_bfloat16* __restrict__ Bh,
                                                  const __nv_bfloat16* __restrict__ Bl,
                                                  float* __restrict__ C,
                                                  int M, int N, int K) {
    extern __shared__ __nv_bfloat16 smem[];
    const uint32_t sbase = smem_u32(smem);

    const int tid = threadIdx.x;
    const int wid = tid >> 5;
    const int lane = tid & 31;
    const int g = lane >> 2;
    const int t = lane & 3;
    const int m0 = blockIdx.y * 128;
    const int n0 = blockIdx.x * 128;
    const int wm = (wid >> 2) * 64;
    const int wn = (wid & 3) * 32;

    // ldmatrix lane addressing (same layouts as validated in attn_tc)
    const int lrow  = (lane & 7) + 8 * ((lane >> 3) & 1);   // A frag
    const int lcol8 = 8 * (lane >> 4);
    const int lrowK = (lane & 7) + 8 * (lane >> 4);          // B frag
    const int lcol8K = 8 * ((lane >> 3) & 1);

    float acc[4][4][4];
#pragma unroll
    for (int mi = 0; mi < 4; mi++)
#pragma unroll
        for (int ni = 0; ni < 4; ni++)
#pragma unroll
            for (int r = 0; r < 4; r++) acc[mi][ni][r] = 0.f;

    const int NIT = K / BKG;

    // Prologue: stage 0
    load_stage(sbase, Ah, Al, Bh, Bl, m0, n0, 0, K, tid);
    asm volatile("cp.async.commit_group;" ::: "memory");

    for (int it = 0; it < NIT; it++) {
        if (it + 1 < NIT) {
            load_stage(sbase + ((it + 1) & 1) * STAGE_ELEM * 2, Ah, Al, Bh, Bl,
                       m0, n0, (it + 1) * BKG, K, tid);
        }
        asm volatile("cp.async.commit_group;" ::: "memory");
        asm volatile("cp.async.wait_group 1;" ::: "memory");
        __syncthreads();

        const uint32_t sAh = sbase + (it & 1) * STAGE_ELEM * 2;
        const uint32_t sAl = sAh + TILE_ELEM * 2;
        const uint32_t sBh = sAh + 2 * TILE_ELEM * 2;
        const uint32_t sBl = sAh + 3 * TILE_ELEM * 2;

#pragma unroll
        for (int ks = 0; ks < 2; ks++) {
            const int kb = ks * 16;
            uint32_t bh[2][4], bl[2][4];
#pragma unroll
            for (int np = 0; np < 2; np++) {
                uint32_t boff = (uint32_t)((wn + np * 16 + lrowK) * (SROW * 2)
                                           + (kb + lcol8K) * 2);
                ldsm_x4(bh[np], sBh + boff);
                ldsm_x4(bl[np], sBl + boff);
            }
#pragma unroll
            for (int mi = 0; mi < 4; mi++) {
                uint32_t ah[4], al[4];
                uint32_t aoff = (uint32_t)((wm + mi * 16 + lrow) * (SROW * 2)
                                           + (kb + lcol8) * 2);
                ldsm_x4(ah, sAh + aoff);
                ldsm_x4(al, sAl + aoff);
#pragma unroll
                for (int np = 0; np < 2; np++) {
                    mma16816(acc[mi][2 * np],     ah, bh[np]);
                    mma16816(acc[mi][2 * np],     ah, bl[np]);
                    mma16816(acc[mi][2 * np],     al, bh[np]);
                    mma16816(acc[mi][2 * np + 1], ah, bh[np] + 2);
                    mma16816(acc[mi][2 * np + 1], ah, bl[np] + 2);
                    mma16816(acc[mi][2 * np + 1], al, bh[np] + 2);
                }
            }
        }
        __syncthreads();
    }

#pragma unroll
    for (int mi = 0; mi < 4; mi++) {
        int row0 = m0 + wm + mi * 16 + g;
#pragma unroll
        for (int ni = 0; ni < 4; ni++) {
            int col = n0 + wn + ni * 8 + 2 * t;
            *(float2*)&C[(size_t)row0 * N + col] =
                make_float2(acc[mi][ni][0], acc[mi][ni][1]);
            *(float2*)&C[(size_t)(row0 + 8) * N + col] =
                make_float2(acc[mi][ni][2], acc[mi][ni][3]);
        }
    }
}

// ---------------------------------------------------------------------------
// Tensor-core causal flash attention. BQ=128, BK=64, Dh=64, 256 threads.
// Q pre-scaled at W-split time. Epilogue writes bf16 hi/lo directly (feeds
// the output projection without an fp32 round-trip).
// ---------------------------------------------------------------------------
#define AT_SMEM 73728

__global__ __launch_bounds__(256) void attn_tc(const float* __restrict__ qkv,
                                               __nv_bfloat16* __restrict__ yh,
                                               __nv_bfloat16* __restrict__ yl) {
    extern __shared__ __nv_bfloat16 asmem[];
    const uint32_t sb = smem_u32(asmem);
    const uint32_t QH = sb, QL = sb + 18432, KH = sb + 36864, KL = sb + 46080,
                   VH = sb + 55296, VL = sb + 64512;

    const int tid = threadIdx.x;
    const int wid = tid >> 5;
    const int lane = tid & 31;
    const int g = lane >> 2, t = lane & 3;
    const int qt = blockIdx.x, h = blockIdx.y, b = blockIdx.z;
    const int q0 = qt * 128;

    const size_t rowstride = 3 * D_MODEL;
    const float* qbase = qkv + (size_t)b * SEQ * rowstride + h * D_HEAD;
    const float* kbase = qbase + D_MODEL;
    const float* vbase = qbase + 2 * D_MODEL;

    const int lrow  = (lane & 7) + 8 * ((lane >> 3) & 1);
    const int lcol8 = 8 * (lane >> 4);
    const int lrowK = (lane & 7) + 8 * (lane >> 4);
    const int lcol8K = 8 * ((lane >> 3) & 1);

    // ---- load + split Q (already scaled via Wqkv) ----
#pragma unroll
    for (int p = 0; p < 8; p++) {
        int v = tid + p * 256;
        int row = v >> 4, c = v & 15;
        float4 q4 = *(const float4*)&qbase[(size_t)(q0 + row) * rowstride + c * 4];
        split_store4(QH + row * 144 + c * 8, QL + row * 144 + c * 8, q4);
    }

    float m_[2] = {-1e30f, -1e30f};
    float l_[2] = {0.f, 0.f};
    float o[8][4];
#pragma unroll
    for (int nt = 0; nt < 8; nt++)
#pragma unroll
        for (int c = 0; c < 4; c++) o[nt][c] = 0.f;

    const int ntiles = 2 * qt + 2;
    for (int kt = 0; kt < ntiles; kt++) {
        __syncthreads();

#pragma unroll
        for (int p = 0; p < 4; p++) {
            int v = tid + p * 256;
            int j = v >> 4, c = v & 15;
            float4 k4 = *(const float4*)&kbase[(size_t)(kt * 64 + j) * rowstride + c * 4];
            split_store4(KH + j * 144 + c * 8, KL + j * 144 + c * 8, k4);
            float4 v4 = *(const float4*)&vbase[(size_t)(kt * 64 + j) * rowstride + c * 4];
            split_store4(VH + j * 144 + c * 8, VL + j * 144 + c * 8, v4);
        }
        __syncthreads();

        float s[8][4];
#pragma unroll
        for (int nt = 0; nt < 8; nt++)
#pragma unroll
            for (int c = 0; c < 4; c++) s[nt][c] = 0.f;

#pragma unroll
        for (int ks = 0; ks < 4; ks++) {
            uint32_t ah[4], al[4];
            uint32_t qoff = (uint32_t)((wid * 16 + lrow) * 144 + (ks * 16 + lcol8) * 2);
            ldsm_x4(ah, QH + qoff);
            ldsm_x4(al, QL + qoff);
#pragma unroll
            for (int ntp = 0; ntp < 4; ntp++) {
                uint32_t bh[4], bl[4];
                uint32_t koff = (uint32_t)((ntp * 16 + lrowK) * 144 + (ks * 16 + lcol8K) * 2);
                ldsm_x4(bh, KH + koff);
                ldsm_x4(bl, KL + koff);
                mma16816(s[2 * ntp],     ah, bh);
                mma16816(s[2 * ntp],     ah, bl);
                mma16816(s[2 * ntp],     al, bh);
                mma16816(s[2 * ntp + 1], ah, bh + 2);
                mma16816(s[2 * ntp + 1], ah, bl + 2);
                mma16816(s[2 * ntp + 1], al, bh + 2);
            }
        }

        if (kt >= 2 * qt) {
#pragma unroll
            for (int nt = 0; nt < 8; nt++)
#pragma unroll
                for (int c = 0; c < 4; c++) {
                    int row = q0 + wid * 16 + g + (c >> 1) * 8;
                    int col = kt * 64 + nt * 8 + 2 * t + (c & 1);
                    if (col > row) s[nt][c] = -1e30f;
                }
        }

#pragma unroll
        for (int r = 0; r < 2; r++) {
            float mx = -1e30f;
#pragma unroll
            for (int nt = 0; nt < 8; nt++)
                mx = fmaxf(mx, fmaxf(s[nt][2 * r], s[nt][2 * r + 1]));
            mx = fmaxf(mx, __shfl_xor_sync(0xffffffffu, mx, 1));
            mx = fmaxf(mx, __shfl_xor_sync(0xffffffffu, mx, 2));
            float mnew = fmaxf(m_[r], mx);
            float corr = __expf(m_[r] - mnew);
            m_[r] = mnew;
            float ls = 0.f;
#pragma unroll
            for (int nt = 0; nt < 8; nt++) {
                float p0 = __expf(s[nt][2 * r] - mnew);
                float p1 = __expf(s[nt][2 * r + 1] - mnew);
                s[nt][2 * r] = p0;
                s[nt][2 * r + 1] = p1;
                ls += p0 + p1;
            }
            ls += __shfl_xor_sync(0xffffffffu, ls, 1);
            ls += __shfl_xor_sync(0xffffffffu, ls, 2);
            l_[r] = l_[r] * corr + ls;
#pragma unroll
            for (int nt = 0; nt < 8; nt++) {
                o[nt][2 * r] *= corr;
                o[nt][2 * r + 1] *= corr;
            }
        }

#pragma unroll
        for (int kc = 0; kc < 4; kc++) {
            uint32_t ah[4], al[4];
            pack_hilo(s[2 * kc][0],     s[2 * kc][1],     ah[0], al[0]);
            pack_hilo(s[2 * kc][2],     s[2 * kc][3],     ah[1], al[1]);
            pack_hilo(s[2 * kc + 1][0], s[2 * kc + 1][1], ah[2], al[2]);
            pack_hilo(s[2 * kc + 1][2], s[2 * kc + 1][3], ah[3], al[3]);
#pragma unroll
            for (int ntp = 0; ntp < 4; ntp++) {
                uint32_t bh[4], bl[4];
                uint32_t voff = (uint32_t)((kc * 16 + lrow) * 144 + (ntp * 16 + lcol8) * 2);
                ldsm_x4_t(bh, VH + voff);
                ldsm_x4_t(bl, VL + voff);
                mma16816(o[2 * ntp],     ah, bh);
                mma16816(o[2 * ntp],     ah, bl);
                mma16816(o[2 * ntp],     al, bh);
                mma16816(o[2 * ntp + 1], ah, bh + 2);
                mma16816(o[2 * ntp + 1], ah, bl + 2);
                mma16816(o[2 * ntp + 1], al, bh + 2);
            }
        }
    }

    // ---- epilogue: normalize + write y as bf16 hi/lo ----
    {
        float inv0 = 1.f / l_[0];
        float inv1 = 1.f / l_[1];
        int row0 = q0 + wid * 16 + g;
        size_t t0 = (size_t)b * SEQ + row0;
#pragma unroll
        for (int nt = 0; nt < 8; nt++) {
            int col = h * D_HEAD + nt * 8 + 2 * t;
            uint32_t hp, lp;
            pack_hilo(o[nt][0] * inv0, o[nt][1] * inv0, hp, lp);
            *(uint32_t*)&yh[t0 * D_MODEL + col] = hp;
            *(uint32_t*)&yl[t0 * D_MODEL + col] = lp;
            pack_hilo(o[nt][2] * inv1, o[nt][3] * inv1, hp, lp);
            *(uint32_t*)&yh[(t0 + 8) * D_MODEL + col] = hp;
            *(uint32_t*)&yl[(t0 + 8) * D_MODEL + col] = lp;
        }
    }
}

// ---------------------------------------------------------------------------
extern "C" void kernel_launch(void* const* d_in, const int* in_sizes, int n_in,
                              void* d_out, int out_size) {
    const float* x    = (const float*)d_in[0];
    const float* Wqkv = (const float*)d_in[1];
    const float* Wout = (const float*)d_in[2];
    float* out = (float*)d_out;

    float* qkv;
    cudaGetSymbolAddress((void**)&qkv, g_qkv);
    __nv_bfloat16 *xh, *xl, *w1h, *w1l, *w2h, *w2l, *yh, *yl;
    cudaGetSymbolAddress((void**)&xh, g_xh);
    cudaGetSymbolAddress((void**)&xl, g_xl);
    cudaGetSymbolAddress((void**)&w1h, g_w1h);
    cudaGetSymbolAddress((void**)&w1l, g_w1l);
    cudaGetSymbolAddress((void**)&w2h, g_w2h);
    cudaGetSymbolAddress((void**)&w2l, g_w2l);
    cudaGetSymbolAddress((void**)&yh, g_yh);
    cudaGetSymbolAddress((void**)&yl, g_yl);

    cudaFuncSetAttribute(gemm_tc, cudaFuncAttributeMaxDynamicSharedMemorySize, GEMM_SMEM);
    cudaFuncSetAttribute(attn_tc, cudaFuncAttributeMaxDynamicSharedMemorySize, AT_SMEM);

    // Splits (Wqkv Q-rows pre-scaled by 1/8 = attention scale, exact)
    {
        int n4 = ROWS * D_MODEL / 4;
        split_bf16<<<(n4 + 255) / 256, 256>>>(x, xh, xl, n4, 0);
        int w1n4 = 3 * D_MODEL * D_MODEL / 4;
        split_bf16<<<(w1n4 + 255) / 256, 256>>>(Wqkv, w1h, w1l, w1n4,
                                                D_MODEL * D_MODEL / 4);
        int w2n4 = D_MODEL * D_MODEL / 4;
        split_bf16<<<(w2n4 + 255) / 256, 256>>>(Wout, w2h, w2l, w2n4, 0);
    }

    // 1) QKV projection: [4096,1024] x [3072,1024]^T
    gemm_tc<<<dim3(3 * D_MODEL / 128, ROWS / 128), 256, GEMM_SMEM>>>(
        xh, xl, w1h, w1l, qkv, ROWS, 3 * D_MODEL, D_MODEL);

    // 2) Tensor-core causal flash attention -> yh/yl bf16 hi/lo
    attn_tc<<<dim3(SEQ / 128, NUM_HEADS, BATCH), 256, AT_SMEM>>>(qkv, yh, yl);

    // 3) Output projection
    gemm_tc<<<dim3(D_MODEL / 128, ROWS / 128), 256, GEMM_SMEM>>>(
        yh, yl, w2h, w2l, out, ROWS, D_MODEL, D_MODEL);
}